// round 16
// baseline (speedup 1.0000x reference)
#include <cuda_runtime.h>
#include <cuda_bf16.h>
#include <cstdint>

// ---------------- problem constants ----------------
static constexpr int B_  = 2;
static constexpr int T_  = 1024;
static constexpr int D_  = 1024;
static constexpr int H_  = 16;
static constexpr int HKV_ = 4;
static constexpr int HD_ = 64;
static constexpr int HG_ = 8;
static constexpr int DV_ = 128;

static constexpr int MT_ = B_*T_;               // 2048 rows
static constexpr int NQKV_ = D_ + 2*HKV_*HD_;   // 1536

// ---------------- scratch ----------------
__device__ float g_qkv[MT_*NQKV_];
__device__ float g_qn[B_*T_*HG_*64];
__device__ float g_kn[B_*T_*HG_*64];
__device__ float g_gdn[B_*T_*D_];               // GDN output (added in Wo epilogue)

// bf16 attention operand planes, layout (b,h,t,d)
__device__ __nv_bfloat16 g_qbh[B_*H_*T_*HD_],  g_qbl[B_*H_*T_*HD_];
__device__ __nv_bfloat16 g_kbh[B_*HKV_*T_*HD_], g_kbl[B_*HKV_*T_*HD_];
__device__ __nv_bfloat16 g_vbh[B_*HKV_*T_*HD_], g_vbl[B_*HKV_*T_*HD_];

// bf16 GEMM planes
__device__ __nv_bfloat16 g_xh[MT_*D_],  g_xl[MT_*D_];
__device__ __nv_bfloat16 g_wh[NQKV_*D_], g_wl[NQKV_*D_];
__device__ __nv_bfloat16 g_woh[D_*D_],  g_wol[D_*D_];
__device__ __nv_bfloat16 g_yh[MT_*D_],  g_yl[MT_*D_];

// ---------------- PTX helpers ----------------
__device__ __forceinline__ uint32_t smem_u32(const void* p) {
    uint32_t a;
    asm("{ .reg .u64 t; cvta.to.shared.u64 t, %1; cvt.u32.u64 %0, t; }" : "=r"(a) : "l"(p));
    return a;
}
__device__ __forceinline__ void ldsm4(uint32_t (&r)[4], uint32_t addr) {
    asm volatile("ldmatrix.sync.aligned.m8n8.x4.shared.b16 {%0,%1,%2,%3}, [%4];"
        : "=r"(r[0]), "=r"(r[1]), "=r"(r[2]), "=r"(r[3]) : "r"(addr));
}
__device__ __forceinline__ void ldsm4t(uint32_t (&r)[4], uint32_t addr) {
    asm volatile("ldmatrix.sync.aligned.m8n8.x4.trans.shared.b16 {%0,%1,%2,%3}, [%4];"
        : "=r"(r[0]), "=r"(r[1]), "=r"(r[2]), "=r"(r[3]) : "r"(addr));
}
__device__ __forceinline__ void mma16816(float (&d)[4], const uint32_t (&a)[4],
                                         const uint32_t* b) {
    asm volatile("mma.sync.aligned.m16n8k16.row.col.f32.bf16.bf16.f32 "
        "{%0,%1,%2,%3}, {%4,%5,%6,%7}, {%8,%9}, {%0,%1,%2,%3};"
        : "+f"(d[0]), "+f"(d[1]), "+f"(d[2]), "+f"(d[3])
        : "r"(a[0]), "r"(a[1]), "r"(a[2]), "r"(a[3]), "r"(b[0]), "r"(b[1]));
}
__device__ __forceinline__ void cp16(uint32_t saddr, const void* gaddr) {
    asm volatile("cp.async.cg.shared.global [%0], [%1], 16;" :: "r"(saddr), "l"(gaddr));
}
__device__ __forceinline__ void cp4(uint32_t saddr, const void* gaddr) {
    asm volatile("cp.async.ca.shared.global [%0], [%1], 4;" :: "r"(saddr), "l"(gaddr));
}
#define CP_COMMIT() asm volatile("cp.async.commit_group;" ::: "memory")
#define CP_WAIT(n)  asm volatile("cp.async.wait_group %0;" :: "n"(n) : "memory")

__device__ __forceinline__ uint32_t packb(float x, float y) {
    __nv_bfloat162 t(__float2bfloat16(x), __float2bfloat16(y));
    return *(uint32_t*)&t;
}

// ---------------- fp32 -> bf16 hi/lo split ----------------
__device__ __forceinline__ void split4(float4 v, __nv_bfloat16* hi, __nv_bfloat16* lo, int i)
{
    __nv_bfloat16 h0 = __float2bfloat16(v.x), h1 = __float2bfloat16(v.y);
    __nv_bfloat16 h2 = __float2bfloat16(v.z), h3 = __float2bfloat16(v.w);
    __nv_bfloat16 l0 = __float2bfloat16(v.x - __bfloat162float(h0));
    __nv_bfloat16 l1 = __float2bfloat16(v.y - __bfloat162float(h1));
    __nv_bfloat16 l2 = __float2bfloat16(v.z - __bfloat162float(h2));
    __nv_bfloat16 l3 = __float2bfloat16(v.w - __bfloat162float(h3));
    ((__nv_bfloat162*)hi)[2*i]   = __nv_bfloat162(h0, h1);
    ((__nv_bfloat162*)hi)[2*i+1] = __nv_bfloat162(h2, h3);
    ((__nv_bfloat162*)lo)[2*i]   = __nv_bfloat162(l0, l1);
    ((__nv_bfloat162*)lo)[2*i+1] = __nv_bfloat162(l2, l3);
}

__global__ void split_bf16(const float* __restrict__ src,
                           __nv_bfloat16* __restrict__ hi,
                           __nv_bfloat16* __restrict__ lo, int n4)
{
    int i = blockIdx.x * 256 + threadIdx.x;
    if (i >= n4) return;
    split4(((const float4*)src)[i], hi, lo, i);
}

__global__ void split_w_qkv(const float* __restrict__ Wq, const float* __restrict__ Wk,
                            const float* __restrict__ Wv,
                            __nv_bfloat16* __restrict__ hi, __nv_bfloat16* __restrict__ lo)
{
    int i = blockIdx.x * 256 + threadIdx.x;
    int e = i * 4;
    int row = e >> 10, col = e & 1023;
    const float* src;
    if (row < D_)               src = Wq + (size_t)row * D_ + col;
    else if (row < D_ + 256)    src = Wk + (size_t)(row - D_) * D_ + col;
    else                        src = Wv + (size_t)(row - D_ - 256) * D_ + col;
    split4(*(const float4*)src, hi, lo, i);
}

// ---------------- mma.sync bf16x2-split GEMM: 128x64 tile, 256 thr, 2-stage ----------------
static constexpr int RS_ = 40;
static constexpr int APL_ = 128 * RS_ * 2;
static constexpr int BPL_ = 64 * RS_ * 2;
static constexpr int STG2_ = 2*APL_ + 2*BPL_;
static constexpr int GEMM_SMEM = 2 * STG2_;

__global__ void __launch_bounds__(256) gemm_mma(
    const __nv_bfloat16* __restrict__ Ah, const __nv_bfloat16* __restrict__ Al,
    const __nv_bfloat16* __restrict__ Bh, const __nv_bfloat16* __restrict__ Bl,
    float* __restrict__ C, const float* __restrict__ Add, int M, int N, int K)
{
    extern __shared__ __align__(128) char smem[];
    const uint32_t sb = smem_u32(smem);
    const int tid = threadIdx.x;
    const int wid = tid >> 5, lane = tid & 31;
    const int wr = wid & 3, wc = wid >> 2;
    const int m0 = blockIdx.y * 128;
    const int n0 = blockIdx.x * 64;
    const int NC = K >> 5;

    const int ar0 = tid >> 2,        ac0 = tid & 3;
    const int ar1 = (tid+256) >> 2,  ac1 = tid & 3;
    const int br  = tid >> 2,        bc  = tid & 3;
    const uint32_t sA0 = (uint32_t)(ar0 * 80 + ac0 * 16);
    const uint32_t sA1 = (uint32_t)(ar1 * 80 + ac1 * 16);
    const uint32_t sB  = (uint32_t)(br  * 80 + bc  * 16);
    const size_t gA0 = (size_t)(m0 + ar0) * K + ac0 * 8;
    const size_t gA1 = (size_t)(m0 + ar1) * K + ac1 * 8;
    const size_t gB  = (size_t)(n0 + br)  * K + bc  * 8;

    auto issue = [&](int kc) {
        uint32_t sd = sb + (kc & 1) * STG2_;
        const int ko = kc * 32;
        cp16(sd + sA0,               Ah + gA0 + ko);
        cp16(sd + sA1,               Ah + gA1 + ko);
        cp16(sd + APL_ + sA0,        Al + gA0 + ko);
        cp16(sd + APL_ + sA1,        Al + gA1 + ko);
        cp16(sd + 2*APL_ + sB,       Bh + gB + ko);
        cp16(sd + 2*APL_ + BPL_ + sB, Bl + gB + ko);
        CP_COMMIT();
    };

    float acc[2][4][4];
#pragma unroll
    for (int mt = 0; mt < 2; mt++)
#pragma unroll
        for (int nt = 0; nt < 4; nt++)
#pragma unroll
            for (int j = 0; j < 4; j++) acc[mt][nt][j] = 0.f;

    issue(0);
    if (NC > 1) issue(1);

    const int lr = lane & 15, lchi = lane >> 4;

    for (int c = 0; c < NC; c++) {
        if (c + 1 < NC) { CP_WAIT(1); } else { CP_WAIT(0); }
        __syncthreads();
        const uint32_t st = sb + (c & 1) * STG2_;
#pragma unroll
        for (int ks = 0; ks < 2; ks++) {
            const int koff = ks * 16 + lchi * 8;
            uint32_t aH[2][4], aL[2][4], bH[4][2], bL[4][2];
#pragma unroll
            for (int mt = 0; mt < 2; mt++) {
                uint32_t ro = (uint32_t)(((wr*32 + mt*16 + lr) * RS_ + koff) * 2);
                ldsm4(aH[mt], st + ro);
                ldsm4(aL[mt], st + APL_ + ro);
            }
#pragma unroll
            for (int np = 0; np < 2; np++) {
                uint32_t ro = (uint32_t)(((wc*32 + np*16 + lr) * RS_ + koff) * 2);
                uint32_t t[4];
                ldsm4(t, st + 2*APL_ + ro);
                bH[np*2+0][0] = t[0]; bH[np*2+0][1] = t[2];
                bH[np*2+1][0] = t[1]; bH[np*2+1][1] = t[3];
                ldsm4(t, st + 2*APL_ + BPL_ + ro);
                bL[np*2+0][0] = t[0]; bL[np*2+0][1] = t[2];
                bL[np*2+1][0] = t[1]; bL[np*2+1][1] = t[3];
            }
#pragma unroll
            for (int mt = 0; mt < 2; mt++)
#pragma unroll
                for (int nt = 0; nt < 4; nt++)
                    mma16816(acc[mt][nt], aH[mt], bH[nt]);
#pragma unroll
            for (int mt = 0; mt < 2; mt++)
#pragma unroll
                for (int nt = 0; nt < 4; nt++)
                    mma16816(acc[mt][nt], aL[mt], bH[nt]);
#pragma unroll
            for (int mt = 0; mt < 2; mt++)
#pragma unroll
                for (int nt = 0; nt < 4; nt++)
                    mma16816(acc[mt][nt], aH[mt], bL[nt]);
        }
        __syncthreads();
        if (c + 2 < NC) issue(c + 2);
    }

    const int er = m0 + wr*32 + (lane >> 2);
    const int ec = n0 + wc*32 + (lane & 3) * 2;
#pragma unroll
    for (int mt = 0; mt < 2; mt++)
#pragma unroll
        for (int nt = 0; nt < 4; nt++) {
            size_t i0 = (size_t)(er + mt*16) * N + ec + nt*8;
            size_t i1 = (size_t)(er + mt*16 + 8) * N + ec + nt*8;
            float2 r0 = make_float2(acc[mt][nt][0], acc[mt][nt][1]);
            float2 r1 = make_float2(acc[mt][nt][2], acc[mt][nt][3]);
            if (Add) {
                float2 a0 = *(const float2*)(Add + i0);
                float2 a1 = *(const float2*)(Add + i1);
                r0.x += a0.x; r0.y += a0.y;
                r1.x += a1.x; r1.y += a1.y;
            }
            *(float2*)(C + i0) = r0;
            *(float2*)(C + i1) = r1;
        }
}

// ---------------- RMSNorm + RoPE -> bf16 hi/lo planes (b,h,t,d) ----------------
__global__ void rmsnorm_rope_bf16(const float* __restrict__ src, int colofs,
                                  __nv_bfloat16* __restrict__ dsth,
                                  __nv_bfloat16* __restrict__ dstl,
                                  const float* __restrict__ gain, int nheads)
{
    int warp = threadIdx.x >> 5, lane = threadIdx.x & 31;
    int item = blockIdx.x*4 + warp;
    int h = item % nheads;
    int row = item / nheads;
    int tpos = row & (T_-1);
    int b = row >> 10;
    const float* p = src + (size_t)row * NQKV_ + colofs + h*64;
    float x1 = p[lane], x2 = p[lane+32];
    float ss = x1*x1 + x2*x2;
#pragma unroll
    for (int o = 16; o > 0; o >>= 1) ss += __shfl_xor_sync(0xffffffffu, ss, o);
    float r = rsqrtf(ss*(1.0f/64.0f) + 1e-6f);
    x1 *= r; x2 *= r;
    float invf = expf(-(float)lane * (9.210340371976184f/32.0f));
    float ang = (float)tpos * invf;
    float sv, cv;
    sincosf(ang, &sv, &cv);
    float g = gain ? gain[h] : 1.0f;
    float o1 = (x1*cv + x2*sv) * g;
    float o2 = (x2*cv - x1*sv) * g;
    size_t base = (((size_t)(b*nheads + h)*T_) + tpos)*64;
    __nv_bfloat16 h1 = __float2bfloat16(o1), h2 = __float2bfloat16(o2);
    dsth[base + lane]      = h1;
    dsth[base + lane + 32] = h2;
    dstl[base + lane]      = __float2bfloat16(o1 - __bfloat162float(h1));
    dstl[base + lane + 32] = __float2bfloat16(o2 - __bfloat162float(h2));
}

// ---------------- V transpose -> bf16 hi/lo (b,h,t,d) ----------------
__global__ void transpose_v_bf16()
{
    int idx = blockIdx.x*256 + threadIdx.x;
    int d = idx & 63;
    int h = (idx >> 6) & 3;
    int t = (idx >> 8) & 1023;
    int b = idx >> 18;
    int row = b*T_ + t;
    float v = g_qkv[(size_t)row * NQKV_ + (D_ + 256) + h*64 + d];
    size_t o = (((size_t)(b*HKV_ + h))*T_ + t)*64 + d;
    __nv_bfloat16 hv = __float2bfloat16(v);
    g_vbh[o] = hv;
    g_vbl[o] = __float2bfloat16(v - __bfloat162float(hv));
}

__global__ void l2norm64(const float* __restrict__ src, float* __restrict__ dst)
{
    int warp = threadIdx.x >> 5, lane = threadIdx.x & 31;
    int item = blockIdx.x*4 + warp;
    const float* p = src + (size_t)item*64;
    float x1 = p[lane], x2 = p[lane+32];
    float ss = x1*x1 + x2*x2;
#pragma unroll
    for (int o = 16; o > 0; o >>= 1) ss += __shfl_xor_sync(0xffffffffu, ss, o);
    float n = sqrtf(ss);
    float r = 1.0f / fmaxf(n, 1e-6f);
    dst[(size_t)item*64 + lane]      = x1*r;
    dst[(size_t)item*64 + lane + 32] = x2*r;
}

// ---------------- flash attention on mma.sync (unchanged) ----------------
static constexpr int ASTRIDE = 72;
static constexpr int AQPL = 64 * ASTRIDE * 2;
static constexpr int AKV0 = 2 * AQPL;
static constexpr int AKVPL = 32 * ASTRIDE * 2;
static constexpr int AKVSTG = 4 * AKVPL;
static constexpr int ATT_SMEM = AKV0 + 3 * AKVSTG;

__global__ void __launch_bounds__(128, 1) attn_mma()
{
    extern __shared__ __align__(128) char sm[];
    const uint32_t sb = smem_u32(sm);
    const int bx = blockIdx.x;
    const int qt = 15 - (bx >> 5);
    const int bh = bx & 31;
    const int b = bh >> 4, h = bh & 15;
    const int tid = threadIdx.x, w = tid >> 5, lane = tid & 31;
    const int gid = lane >> 2, tig = lane & 3;
    const int nkt = 2 * (qt + 1);
    const int row_base = qt*64 + w*16;

    const __nv_bfloat16* qsh = g_qbh + (((size_t)(b*H_ + h)*T_) + qt*64)*64;
    const __nv_bfloat16* qsl = g_qbl + (((size_t)(b*H_ + h)*T_) + qt*64)*64;
    const __nv_bfloat16* ksh = g_kbh + ((size_t)(b*HKV_ + (h>>2))*T_)*64;
    const __nv_bfloat16* ksl = g_kbl + ((size_t)(b*HKV_ + (h>>2))*T_)*64;
    const __nv_bfloat16* vsh = g_vbh + ((size_t)(b*HKV_ + (h>>2))*T_)*64;
    const __nv_bfloat16* vsl = g_vbl + ((size_t)(b*HKV_ + (h>>2))*T_)*64;

#pragma unroll
    for (int i = 0; i < 8; i++) {
        int idx = tid + i*128;
        int plane = idx >> 9, rem = idx & 511;
        int r = rem >> 3, c = rem & 7;
        const __nv_bfloat16* src = plane ? qsl : qsh;
        cp16(sb + plane*AQPL + r*144 + c*16, src + r*64 + c*8);
    }
    CP_COMMIT();

    auto loadkv = [&](int kt) {
        uint32_t base = sb + AKV0 + (kt % 3) * AKVSTG;
        const __nv_bfloat16* srcs[4] = { ksh, ksl, vsh, vsl };
#pragma unroll
        for (int p = 0; p < 4; p++) {
#pragma unroll
            for (int i = 0; i < 2; i++) {
                int idx = tid + i*128;
                int r = idx >> 3, c = idx & 7;
                cp16(base + p*AKVPL + r*144 + c*16, srcs[p] + (size_t)(kt*32 + r)*64 + c*8);
            }
        }
        CP_COMMIT();
    };

    loadkv(0);
    loadkv(1);

    CP_WAIT(2);
    __syncthreads();
    uint32_t QH[4][4], QL[4][4];
    {
        const uint32_t qro = (uint32_t)((w*16 + (lane & 15)) * 144 + ((lane >> 4) & 1) * 16);
#pragma unroll
        for (int kc = 0; kc < 4; kc++) {
            ldsm4(QH[kc], sb + 0*AQPL + qro + kc*32);
            ldsm4(QL[kc], sb + 1*AQPL + qro + kc*32);
        }
    }

    float o[8][4];
#pragma unroll
    for (int dn = 0; dn < 8; dn++)
#pragma unroll
        for (int j = 0; j < 4; j++) o[dn][j] = 0.f;
    float m0 = -1e30f, m1 = -1e30f, l0 = 0.f, l1 = 0.f;

    const uint32_t kro_base = (uint32_t)(((lane & 7) + ((lane >> 4) & 1) * 8) * 144
                                         + ((lane >> 3) & 1) * 16);
    const uint32_t vro_base = (uint32_t)(((lane & 7) + ((lane >> 3) & 1) * 8) * 144
                                         + ((lane >> 4) & 1) * 16);

    for (int kt = 0; kt < nkt; kt++) {
        if (kt + 1 < nkt) { CP_WAIT(1); } else { CP_WAIT(0); }
        __syncthreads();
        if (kt + 2 < nkt) loadkv(kt + 2);

        const int kt0 = kt * 32;
        if (kt0 > row_base + 15) continue;

        const uint32_t kvb = sb + AKV0 + (kt % 3) * AKVSTG;

        float acc[4][4];
#pragma unroll
        for (int nt = 0; nt < 4; nt++)
#pragma unroll
            for (int j = 0; j < 4; j++) acc[nt][j] = 0.f;

#pragma unroll
        for (int kc = 0; kc < 4; kc++) {
            uint32_t a0 = kvb + kro_base + kc*32;
            uint32_t a1 = a0 + 16*144;
            uint32_t h0[4], l0f[4], h1[4], l1f[4];
            ldsm4(h0, a0);
            ldsm4(l0f, a0 + AKVPL);
            ldsm4(h1, a1);
            ldsm4(l1f, a1 + AKVPL);
            mma16816(acc[0], QH[kc], &h0[0]);
            mma16816(acc[1], QH[kc], &h0[2]);
            mma16816(acc[2], QH[kc], &h1[0]);
            mma16816(acc[3], QH[kc], &h1[2]);
            mma16816(acc[0], QL[kc], &h0[0]);
            mma16816(acc[1], QL[kc], &h0[2]);
            mma16816(acc[2], QL[kc], &h1[0]);
            mma16816(acc[3], QL[kc], &h1[2]);
            mma16816(acc[0], QH[kc], &l0f[0]);
            mma16816(acc[1], QH[kc], &l0f[2]);
            mma16816(acc[2], QH[kc], &l1f[0]);
            mma16816(acc[3], QH[kc], &l1f[2]);
        }

        const int row0 = row_base + gid, row1 = row0 + 8;
        const bool domask = (kt0 + 31 > row_base);
#pragma unroll
        for (int nt = 0; nt < 4; nt++) {
            int kcol = kt0 + nt*8 + tig*2;
#pragma unroll
            for (int j = 0; j < 4; j++) acc[nt][j] *= 0.125f;
            if (domask) {
                if (kcol     > row0) acc[nt][0] = -1e30f;
                if (kcol + 1 > row0) acc[nt][1] = -1e30f;
                if (kcol     > row1) acc[nt][2] = -1e30f;
                if (kcol + 1 > row1) acc[nt][3] = -1e30f;
            }
        }

        float mx0 = -1e30f, mx1 = -1e30f;
#pragma unroll
        for (int nt = 0; nt < 4; nt++) {
            mx0 = fmaxf(mx0, fmaxf(acc[nt][0], acc[nt][1]));
            mx1 = fmaxf(mx1, fmaxf(acc[nt][2], acc[nt][3]));
        }
        mx0 = fmaxf(mx0, __shfl_xor_sync(0xffffffffu, mx0, 1));
        mx0 = fmaxf(mx0, __shfl_xor_sync(0xffffffffu, mx0, 2));
        mx1 = fmaxf(mx1, __shfl_xor_sync(0xffffffffu, mx1, 1));
        mx1 = fmaxf(mx1, __shfl_xor_sync(0xffffffffu, mx1, 2));
        float m0n = fmaxf(m0, mx0), m1n = fmaxf(m1, mx1);
        float c0r = __expf(m0 - m0n), c1r = __expf(m1 - m1n);
        m0 = m0n; m1 = m1n;
        l0 *= c0r; l1 *= c1r;
#pragma unroll
        for (int dn = 0; dn < 8; dn++) {
            o[dn][0] *= c0r; o[dn][1] *= c0r;
            o[dn][2] *= c1r; o[dn][3] *= c1r;
        }
        float s0 = 0.f, s1 = 0.f;
#pragma unroll
        for (int nt = 0; nt < 4; nt++) {
            acc[nt][0] = __expf(acc[nt][0] - m0);
            acc[nt][1] = __expf(acc[nt][1] - m0);
            acc[nt][2] = __expf(acc[nt][2] - m1);
            acc[nt][3] = __expf(acc[nt][3] - m1);
            s0 += acc[nt][0] + acc[nt][1];
            s1 += acc[nt][2] + acc[nt][3];
        }
        s0 += __shfl_xor_sync(0xffffffffu, s0, 1);
        s0 += __shfl_xor_sync(0xffffffffu, s0, 2);
        s1 += __shfl_xor_sync(0xffffffffu, s1, 1);
        s1 += __shfl_xor_sync(0xffffffffu, s1, 2);
        l0 += s0; l1 += s1;

        uint32_t PH[2][4], PL[2][4];
#pragma unroll
        for (int kk = 0; kk < 2; kk++) {
            float p00 = acc[2*kk][0],   p01 = acc[2*kk][1];
            float p02 = acc[2*kk][2],   p03 = acc[2*kk][3];
            float p10 = acc[2*kk+1][0], p11 = acc[2*kk+1][1];
            float p12 = acc[2*kk+1][2], p13 = acc[2*kk+1][3];
            PH[kk][0] = packb(p00, p01);
            PH[kk][1] = packb(p02, p03);
            PH[kk][2] = packb(p10, p11);
            PH[kk][3] = packb(p12, p13);
            PL[kk][0] = packb(p00 - __bfloat162float(__float2bfloat16(p00)),
                              p01 - __bfloat162float(__float2bfloat16(p01)));
            PL[kk][1] = packb(p02 - __bfloat162float(__float2bfloat16(p02)),
                              p03 - __bfloat162float(__float2bfloat16(p03)));
            PL[kk][2] = packb(p10 - __bfloat162float(__float2bfloat16(p10)),
                              p11 - __bfloat162float(__float2bfloat16(p11)));
            PL[kk][3] = packb(p12 - __bfloat162float(__float2bfloat16(p12)),
                              p13 - __bfloat162float(__float2bfloat16(p13)));
        }

#pragma unroll
        for (int kk = 0; kk < 2; kk++) {
#pragma unroll
            for (int dcp = 0; dcp < 2; dcp++) {
                uint32_t aA = kvb + 2*AKVPL + vro_base + kk*16*144 + (dcp*2)*32;
                uint32_t aB = aA + 32;
                uint32_t vhA[4], vlA[4], vhB[4], vlB[4];
                ldsm4t(vhA, aA);
                ldsm4t(vlA, aA + AKVPL);
                ldsm4t(vhB, aB);
                ldsm4t(vlB, aB + AKVPL);
                float (&oA0)[4] = o[dcp*4+0];
                float (&oA1)[4] = o[dcp*4+1];
                float (&oB0)[4] = o[dcp*4+2];
                float (&oB1)[4] = o[dcp*4+3];
                mma16816(oA0, PH[kk], &vhA[0]);
                mma16816(oA1, PH[kk], &vhA[2]);
                mma16816(oB0, PH[kk], &vhB[0]);
                mma16816(oB1, PH[kk], &vhB[2]);
                mma16816(oA0, PL[kk], &vhA[0]);
                mma16816(oA1, PL[kk], &vhA[2]);
                mma16816(oB0, PL[kk], &vhB[0]);
                mma16816(oB1, PL[kk], &vhB[2]);
                mma16816(oA0, PH[kk], &vlA[0]);
                mma16816(oA1, PH[kk], &vlA[2]);
                mma16816(oB0, PH[kk], &vlB[0]);
                mma16816(oB1, PH[kk], &vlB[2]);
            }
        }
    }

    const float i0 = 1.f / l0, i1 = 1.f / l1;
    const int grow0 = b*T_ + row_base + gid;
#pragma unroll
    for (int dn = 0; dn < 8; dn++) {
        int dcp = dn >> 2, sub = dn & 3;
        int col = h*64 + dcp*32 + sub*8 + tig*2;
        float a0 = o[dn][0]*i0, a1 = o[dn][1]*i0;
        float a2 = o[dn][2]*i1, a3 = o[dn][3]*i1;
        __nv_bfloat16 h0 = __float2bfloat16(a0), h1 = __float2bfloat16(a1);
        __nv_bfloat16 h2 = __float2bfloat16(a2), h3 = __float2bfloat16(a3);
        size_t p0 = (size_t)grow0 * D_ + col;
        size_t p1 = (size_t)(grow0 + 8) * D_ + col;
        *(__nv_bfloat162*)(g_yh + p0) = __nv_bfloat162(h0, h1);
        *(__nv_bfloat162*)(g_yh + p1) = __nv_bfloat162(h2, h3);
        *(__nv_bfloat162*)(g_yl + p0) = __nv_bfloat162(
            __float2bfloat16(a0 - __bfloat162float(h0)),
            __float2bfloat16(a1 - __bfloat162float(h1)));
        *(__nv_bfloat162*)(g_yl + p1) = __nv_bfloat162(
            __float2bfloat16(a2 - __bfloat162float(h2)),
            __float2bfloat16(a3 - __bfloat162float(h3)));
    }
}

// ---------------- GDN v6s: deferred-output pipeline, 32-step chunks (37.4KB smem) ----------------
static constexpr int GDN_CH = 32;
static constexpr int GDN_KS = 0;                    // k: 32 x 64 f32 = 8192 B
static constexpr int GDN_QS = 8192;                 // q: 8192 B
static constexpr int GDN_VS = 16384;                // v: 32 x 16 f32 = 2048 B
static constexpr int GDN_AS = 18432;                // alpha: 128 B
static constexpr int GDN_BS = 18560;                // beta: 128 B
static constexpr int GDN_BUF = 18688;
static constexpr int GDN_SMEM = 2 * GDN_BUF;        // 37376 B

__global__ void __launch_bounds__(128) gdn_kernel(const float* __restrict__ gv,
    const float* __restrict__ alpha, const float* __restrict__ beta,
    float* __restrict__ gout)
{
    extern __shared__ __align__(16) char sm[];
    const int bh = blockIdx.x >> 3;
    const int cc = blockIdx.x & 7;
    const int b = bh >> 3, h = bh & 7;
    const int tid = threadIdx.x;
    const int coll = tid >> 3;
    const int col = cc*16 + coll;
    const int e = tid & 7;

    const float* kbase = g_kn + ((size_t)(b*T_)*HG_ + h)*64;
    const float* qbase = g_qn + ((size_t)(b*T_)*HG_ + h)*64;
    const float* vbase = gv    + ((size_t)(b*T_)*HG_ + h)*128 + cc*16;
    const float* abase = alpha + (size_t)b*T_*HG_ + h;
    const float* bbase = beta  + (size_t)b*T_*HG_ + h;
    float* op = gout + (size_t)b*T_*D_ + h*DV_ + col;

    const uint32_t sb = smem_u32(sm);

    auto issue = [&](int ch) {
        uint32_t dst = sb + (uint32_t)(ch & 1) * GDN_BUF;
        const int t0 = ch * GDN_CH;
#pragma unroll
        for (int i = 0; i < 4; i++) {               // k,q: 512 x 16B each
            int idx = tid + i*128;
            int r = idx >> 4, c = idx & 15;
            cp16(dst + GDN_KS + (uint32_t)(r*256 + c*16), kbase + (size_t)(t0+r)*512 + c*4);
            cp16(dst + GDN_QS + (uint32_t)(r*256 + c*16), qbase + (size_t)(t0+r)*512 + c*4);
        }
        {                                           // v: 128 x 16B
            int r = tid >> 2, c = tid & 3;
            cp16(dst + GDN_VS + (uint32_t)(r*64 + c*16), vbase + (size_t)(t0+r)*1024 + c*4);
        }
        if (tid < 32) {
            cp4(dst + GDN_AS + (uint32_t)tid*4, abase + (size_t)(t0+tid)*8);
            cp4(dst + GDN_BS + (uint32_t)tid*4, bbase + (size_t)(t0+tid)*8);
        }
        CP_COMMIT();
    };

    float S[8];
#pragma unroll
    for (int i = 0; i < 8; i++) S[i] = 0.f;
    float pdot = 0.f;

    issue(0);
    issue(1);
    const int NCH = T_ / GDN_CH;                    // 32

    for (int ch = 0; ch < NCH; ch++) {
        if (ch + 1 < NCH) { CP_WAIT(1); } else { CP_WAIT(0); }
        __syncthreads();
        const char* bufp = sm + (ch & 1) * GDN_BUF;
        const float* sk = (const float*)(bufp + GDN_KS);
        const float* sq = (const float*)(bufp + GDN_QS);
        const float* sv = (const float*)(bufp + GDN_VS);
        const float* sa = (const float*)(bufp + GDN_AS);
        const float* sbt = (const float*)(bufp + GDN_BS);

        float4 ck0 = *(const float4*)(sk + e*8);
        float4 ck1 = *(const float4*)(sk + e*8 + 4);
        float4 cq0 = *(const float4*)(sq + e*8);
        float4 cq1 = *(const float4*)(sq + e*8 + 4);
        float cv = sv[coll];
        float ca = sa[0], cb = sbt[0];

#pragma unroll 4
        for (int t = 0; t < GDN_CH; t++) {
            float4 nk0 = ck0, nk1 = ck1, nq0 = cq0, nq1 = cq1;
            float nv = cv, na = ca, nb = cb;
            if (t + 1 < GDN_CH) {
                nk0 = *(const float4*)(sk + (t+1)*64 + e*8);
                nk1 = *(const float4*)(sk + (t+1)*64 + e*8 + 4);
                nq0 = *(const float4*)(sq + (t+1)*64 + e*8);
                nq1 = *(const float4*)(sq + (t+1)*64 + e*8 + 4);
                nv = sv[(t+1)*16 + coll];
                na = sa[t+1]; nb = sbt[t+1];
            }

            float d0 = ck0.x*S[0] + ck0.y*S[1];
            float d1 = ck0.z*S[2] + ck0.w*S[3];
            float d2 = ck1.x*S[4] + ck1.y*S[5];
            float d3 = ck1.z*S[6] + ck1.w*S[7];
            float kS = (d0+d1) + (d2+d3);

            float p0 = ca*S[0], p1 = ca*S[1], p2 = ca*S[2], p3 = ca*S[3];
            float p4 = ca*S[4], p5 = ca*S[5], p6 = ca*S[6], p7 = ca*S[7];

            float s1 = __shfl_xor_sync(0xffffffffu, kS, 1);
            float r1 = __shfl_xor_sync(0xffffffffu, pdot, 1);
            kS += s1; pdot += r1;
            float s2 = __shfl_xor_sync(0xffffffffu, kS, 2);
            float r2 = __shfl_xor_sync(0xffffffffu, pdot, 2);
            kS += s2; pdot += r2;
            float s4 = __shfl_xor_sync(0xffffffffu, kS, 4);
            float r4 = __shfl_xor_sync(0xffffffffu, pdot, 4);
            kS += s4; pdot += r4;

            const int gt = ch*GDN_CH + t;
            if (e == 0 && gt > 0) op[(size_t)(gt-1) * D_] = pdot;

            float coef = fmaf(-ca*cb, kS, cv);
            S[0] = fmaf(coef, ck0.x, p0);
            S[1] = fmaf(coef, ck0.y, p1);
            S[2] = fmaf(coef, ck0.z, p2);
            S[3] = fmaf(coef, ck0.w, p3);
            S[4] = fmaf(coef, ck1.x, p4);
            S[5] = fmaf(coef, ck1.y, p5);
            S[6] = fmaf(coef, ck1.z, p6);
            S[7] = fmaf(coef, ck1.w, p7);

            float e0 = S[0]*cq0.x + S[1]*cq0.y;
            float e1 = S[2]*cq0.z + S[3]*cq0.w;
            float e2 = S[4]*cq1.x + S[5]*cq1.y;
            float e3 = S[6]*cq1.z + S[7]*cq1.w;
            pdot = (e0+e1) + (e2+e3);

            ck0 = nk0; ck1 = nk1; cq0 = nq0; cq1 = nq1;
            cv = nv; ca = na; cb = nb;
        }
        __syncthreads();
        if (ch + 2 < NCH) issue(ch + 2);
    }

    pdot += __shfl_xor_sync(0xffffffffu, pdot, 1);
    pdot += __shfl_xor_sync(0xffffffffu, pdot, 2);
    pdot += __shfl_xor_sync(0xffffffffu, pdot, 4);
    if (e == 0) op[(size_t)(T_-1) * D_] = pdot;
}

// ---------------- launch: two-stream fork with low-footprint GDN ----------------
extern "C" void kernel_launch(void* const* d_in, const int* in_sizes, int n_in,
                              void* d_out, int out_size)
{
    const float* x     = (const float*)d_in[0];
    const float* Wq    = (const float*)d_in[1];
    const float* Wk    = (const float*)d_in[2];
    const float* Wv    = (const float*)d_in[3];
    const float* Wo    = (const float*)d_in[4];
    const float* qg    = (const float*)d_in[5];
    const float* gq    = (const float*)d_in[6];
    const float* gk    = (const float*)d_in[7];
    const float* gv    = (const float*)d_in[8];
    const float* alpha = (const float*)d_in[9];
    const float* beta  = (const float*)d_in[10];
    float* out = (float*)d_out;

    float *qkv,*qn,*kn,*gdn;
    cudaGetSymbolAddress((void**)&qkv, g_qkv);
    cudaGetSymbolAddress((void**)&qn, g_qn);
    cudaGetSymbolAddress((void**)&kn, g_kn);
    cudaGetSymbolAddress((void**)&gdn, g_gdn);

    __nv_bfloat16 *xh,*xl,*wh,*wl,*woh,*wol,*yh,*yl,*qbh,*qbl,*kbh,*kbl;
    cudaGetSymbolAddress((void**)&xh, g_xh);   cudaGetSymbolAddress((void**)&xl, g_xl);
    cudaGetSymbolAddress((void**)&wh, g_wh);   cudaGetSymbolAddress((void**)&wl, g_wl);
    cudaGetSymbolAddress((void**)&woh, g_woh); cudaGetSymbolAddress((void**)&wol, g_wol);
    cudaGetSymbolAddress((void**)&yh, g_yh);   cudaGetSymbolAddress((void**)&yl, g_yl);
    cudaGetSymbolAddress((void**)&qbh, g_qbh); cudaGetSymbolAddress((void**)&qbl, g_qbl);
    cudaGetSymbolAddress((void**)&kbh, g_kbh); cudaGetSymbolAddress((void**)&kbl, g_kbl);

    cudaFuncSetAttribute(gemm_mma, cudaFuncAttributeMaxDynamicSharedMemorySize, GEMM_SMEM);
    cudaFuncSetAttribute(attn_mma, cudaFuncAttributeMaxDynamicSharedMemorySize, ATT_SMEM);
    cudaFuncSetAttribute(gdn_kernel, cudaFuncAttributeMaxDynamicSharedMemorySize, GDN_SMEM);

    cudaStream_t s2;
    cudaEvent_t evFork, evJoin;
    cudaStreamCreateWithFlags(&s2, cudaStreamNonBlocking);
    cudaEventCreateWithFlags(&evFork, cudaEventDisableTiming);
    cudaEventCreateWithFlags(&evJoin, cudaEventDisableTiming);

    cudaEventRecord(evFork, 0);
    cudaStreamWaitEvent(s2, evFork, 0);

    // ---- GDN branch + Wo weight split on s2 ----
    l2norm64<<<(B_*T_*HG_)/4, 128, 0, s2>>>(gq, qn);
    l2norm64<<<(B_*T_*HG_)/4, 128, 0, s2>>>(gk, kn);
    split_bf16<<<D_*D_/4/256, 256, 0, s2>>>(Wo, woh, wol, D_*D_/4);
    gdn_kernel<<<128, 128, GDN_SMEM, s2>>>(gv, alpha, beta, gdn);
    cudaEventRecord(evJoin, s2);

    // ---- attention branch on default stream ----
    split_w_qkv<<<NQKV_*D_/4/256, 256>>>(Wq, Wk, Wv, wh, wl);
    split_bf16<<<MT_*D_/4/256, 256>>>(x, xh, xl, MT_*D_/4);

    gemm_mma<<<dim3(NQKV_/64, MT_/128), 256, GEMM_SMEM>>>(
        xh, xl, wh, wl, qkv, (const float*)nullptr, MT_, NQKV_, D_);

    rmsnorm_rope_bf16<<<(B_*T_*H_)/4, 128>>>(qkv, 0, qbh, qbl, qg, H_);
    rmsnorm_rope_bf16<<<(B_*T_*HKV_)/4, 128>>>(qkv, D_, kbh, kbl, (const float*)nullptr, HKV_);
    transpose_v_bf16<<<(B_*T_*HKV_*HD_)/256, 256>>>();

    attn_mma<<<512, 128, ATT_SMEM>>>();

    // ---- join: Wo projection + GDN add needs both branches ----
    cudaStreamWaitEvent(0, evJoin, 0);
    gemm_mma<<<dim3(D_/64, MT_/128), 256, GEMM_SMEM>>>(
        yh, yl, woh, wol, out, gdn, MT_, D_, D_);
}

// round 17
// speedup vs baseline: 1.8758x; 1.8758x over previous
#include <cuda_runtime.h>
#include <cuda_bf16.h>
#include <cstdint>

// ---------------- problem constants ----------------
static constexpr int B_  = 2;
static constexpr int T_  = 1024;
static constexpr int D_  = 1024;
static constexpr int H_  = 16;
static constexpr int HKV_ = 4;
static constexpr int HD_ = 64;
static constexpr int HG_ = 8;
static constexpr int DV_ = 128;

static constexpr int MT_ = B_*T_;               // 2048 rows
static constexpr int NQKV_ = D_ + 2*HKV_*HD_;   // 1536

// ---------------- scratch ----------------
__device__ float g_qkv[MT_*NQKV_];
__device__ float g_qn[B_*T_*HG_*64];
__device__ float g_kn[B_*T_*HG_*64];
__device__ float g_gdn[B_*T_*D_];               // GDN output (added in Wo epilogue)

// bf16 attention operand planes, layout (b,h,t,d)
__device__ __nv_bfloat16 g_qbh[B_*H_*T_*HD_],  g_qbl[B_*H_*T_*HD_];
__device__ __nv_bfloat16 g_kbh[B_*HKV_*T_*HD_], g_kbl[B_*HKV_*T_*HD_];
__device__ __nv_bfloat16 g_vbh[B_*HKV_*T_*HD_], g_vbl[B_*HKV_*T_*HD_];

// bf16 GEMM planes
__device__ __nv_bfloat16 g_xh[MT_*D_],  g_xl[MT_*D_];
__device__ __nv_bfloat16 g_wh[NQKV_*D_], g_wl[NQKV_*D_];
__device__ __nv_bfloat16 g_woh[D_*D_],  g_wol[D_*D_];
__device__ __nv_bfloat16 g_yh[MT_*D_],  g_yl[MT_*D_];

// ---------------- PTX helpers ----------------
__device__ __forceinline__ uint32_t smem_u32(const void* p) {
    uint32_t a;
    asm("{ .reg .u64 t; cvta.to.shared.u64 t, %1; cvt.u32.u64 %0, t; }" : "=r"(a) : "l"(p));
    return a;
}
__device__ __forceinline__ void ldsm4(uint32_t (&r)[4], uint32_t addr) {
    asm volatile("ldmatrix.sync.aligned.m8n8.x4.shared.b16 {%0,%1,%2,%3}, [%4];"
        : "=r"(r[0]), "=r"(r[1]), "=r"(r[2]), "=r"(r[3]) : "r"(addr));
}
__device__ __forceinline__ void ldsm4t(uint32_t (&r)[4], uint32_t addr) {
    asm volatile("ldmatrix.sync.aligned.m8n8.x4.trans.shared.b16 {%0,%1,%2,%3}, [%4];"
        : "=r"(r[0]), "=r"(r[1]), "=r"(r[2]), "=r"(r[3]) : "r"(addr));
}
__device__ __forceinline__ void mma16816(float (&d)[4], const uint32_t (&a)[4],
                                         const uint32_t* b) {
    asm volatile("mma.sync.aligned.m16n8k16.row.col.f32.bf16.bf16.f32 "
        "{%0,%1,%2,%3}, {%4,%5,%6,%7}, {%8,%9}, {%0,%1,%2,%3};"
        : "+f"(d[0]), "+f"(d[1]), "+f"(d[2]), "+f"(d[3])
        : "r"(a[0]), "r"(a[1]), "r"(a[2]), "r"(a[3]), "r"(b[0]), "r"(b[1]));
}
__device__ __forceinline__ void cp16(uint32_t saddr, const void* gaddr) {
    asm volatile("cp.async.cg.shared.global [%0], [%1], 16;" :: "r"(saddr), "l"(gaddr));
}
__device__ __forceinline__ void cp4(uint32_t saddr, const void* gaddr) {
    asm volatile("cp.async.ca.shared.global [%0], [%1], 4;" :: "r"(saddr), "l"(gaddr));
}
#define CP_COMMIT() asm volatile("cp.async.commit_group;" ::: "memory")
#define CP_WAIT(n)  asm volatile("cp.async.wait_group %0;" :: "n"(n) : "memory")

__device__ __forceinline__ uint32_t packb(float x, float y) {
    __nv_bfloat162 t(__float2bfloat16(x), __float2bfloat16(y));
    return *(uint32_t*)&t;
}

// ---------------- fp32 -> bf16 hi/lo split ----------------
__device__ __forceinline__ void split4(float4 v, __nv_bfloat16* hi, __nv_bfloat16* lo, int i)
{
    __nv_bfloat16 h0 = __float2bfloat16(v.x), h1 = __float2bfloat16(v.y);
    __nv_bfloat16 h2 = __float2bfloat16(v.z), h3 = __float2bfloat16(v.w);
    __nv_bfloat16 l0 = __float2bfloat16(v.x - __bfloat162float(h0));
    __nv_bfloat16 l1 = __float2bfloat16(v.y - __bfloat162float(h1));
    __nv_bfloat16 l2 = __float2bfloat16(v.z - __bfloat162float(h2));
    __nv_bfloat16 l3 = __float2bfloat16(v.w - __bfloat162float(h3));
    ((__nv_bfloat162*)hi)[2*i]   = __nv_bfloat162(h0, h1);
    ((__nv_bfloat162*)hi)[2*i+1] = __nv_bfloat162(h2, h3);
    ((__nv_bfloat162*)lo)[2*i]   = __nv_bfloat162(l0, l1);
    ((__nv_bfloat162*)lo)[2*i+1] = __nv_bfloat162(l2, l3);
}

__global__ void split_bf16(const float* __restrict__ src,
                           __nv_bfloat16* __restrict__ hi,
                           __nv_bfloat16* __restrict__ lo, int n4)
{
    int i = blockIdx.x * 256 + threadIdx.x;
    if (i >= n4) return;
    split4(((const float4*)src)[i], hi, lo, i);
}

__global__ void split_w_qkv(const float* __restrict__ Wq, const float* __restrict__ Wk,
                            const float* __restrict__ Wv,
                            __nv_bfloat16* __restrict__ hi, __nv_bfloat16* __restrict__ lo)
{
    int i = blockIdx.x * 256 + threadIdx.x;
    int e = i * 4;
    int row = e >> 10, col = e & 1023;
    const float* src;
    if (row < D_)               src = Wq + (size_t)row * D_ + col;
    else if (row < D_ + 256)    src = Wk + (size_t)(row - D_) * D_ + col;
    else                        src = Wv + (size_t)(row - D_ - 256) * D_ + col;
    split4(*(const float4*)src, hi, lo, i);
}

// ---------------- mma.sync bf16x2-split GEMM: 128x64 tile, 256 thr, 2-stage ----------------
static constexpr int RS_ = 40;
static constexpr int APL_ = 128 * RS_ * 2;
static constexpr int BPL_ = 64 * RS_ * 2;
static constexpr int STG2_ = 2*APL_ + 2*BPL_;
static constexpr int GEMM_SMEM = 2 * STG2_;

__global__ void __launch_bounds__(256) gemm_mma(
    const __nv_bfloat16* __restrict__ Ah, const __nv_bfloat16* __restrict__ Al,
    const __nv_bfloat16* __restrict__ Bh, const __nv_bfloat16* __restrict__ Bl,
    float* __restrict__ C, const float* __restrict__ Add, int M, int N, int K)
{
    extern __shared__ __align__(128) char smem[];
    const uint32_t sb = smem_u32(smem);
    const int tid = threadIdx.x;
    const int wid = tid >> 5, lane = tid & 31;
    const int wr = wid & 3, wc = wid >> 2;
    const int m0 = blockIdx.y * 128;
    const int n0 = blockIdx.x * 64;
    const int NC = K >> 5;

    const int ar0 = tid >> 2,        ac0 = tid & 3;
    const int ar1 = (tid+256) >> 2,  ac1 = tid & 3;
    const int br  = tid >> 2,        bc  = tid & 3;
    const uint32_t sA0 = (uint32_t)(ar0 * 80 + ac0 * 16);
    const uint32_t sA1 = (uint32_t)(ar1 * 80 + ac1 * 16);
    const uint32_t sB  = (uint32_t)(br  * 80 + bc  * 16);
    const size_t gA0 = (size_t)(m0 + ar0) * K + ac0 * 8;
    const size_t gA1 = (size_t)(m0 + ar1) * K + ac1 * 8;
    const size_t gB  = (size_t)(n0 + br)  * K + bc  * 8;

    auto issue = [&](int kc) {
        uint32_t sd = sb + (kc & 1) * STG2_;
        const int ko = kc * 32;
        cp16(sd + sA0,               Ah + gA0 + ko);
        cp16(sd + sA1,               Ah + gA1 + ko);
        cp16(sd + APL_ + sA0,        Al + gA0 + ko);
        cp16(sd + APL_ + sA1,        Al + gA1 + ko);
        cp16(sd + 2*APL_ + sB,       Bh + gB + ko);
        cp16(sd + 2*APL_ + BPL_ + sB, Bl + gB + ko);
        CP_COMMIT();
    };

    float acc[2][4][4];
#pragma unroll
    for (int mt = 0; mt < 2; mt++)
#pragma unroll
        for (int nt = 0; nt < 4; nt++)
#pragma unroll
            for (int j = 0; j < 4; j++) acc[mt][nt][j] = 0.f;

    issue(0);
    if (NC > 1) issue(1);

    const int lr = lane & 15, lchi = lane >> 4;

    for (int c = 0; c < NC; c++) {
        if (c + 1 < NC) { CP_WAIT(1); } else { CP_WAIT(0); }
        __syncthreads();
        const uint32_t st = sb + (c & 1) * STG2_;
#pragma unroll
        for (int ks = 0; ks < 2; ks++) {
            const int koff = ks * 16 + lchi * 8;
            uint32_t aH[2][4], aL[2][4], bH[4][2], bL[4][2];
#pragma unroll
            for (int mt = 0; mt < 2; mt++) {
                uint32_t ro = (uint32_t)(((wr*32 + mt*16 + lr) * RS_ + koff) * 2);
                ldsm4(aH[mt], st + ro);
                ldsm4(aL[mt], st + APL_ + ro);
            }
#pragma unroll
            for (int np = 0; np < 2; np++) {
                uint32_t ro = (uint32_t)(((wc*32 + np*16 + lr) * RS_ + koff) * 2);
                uint32_t t[4];
                ldsm4(t, st + 2*APL_ + ro);
                bH[np*2+0][0] = t[0]; bH[np*2+0][1] = t[2];
                bH[np*2+1][0] = t[1]; bH[np*2+1][1] = t[3];
                ldsm4(t, st + 2*APL_ + BPL_ + ro);
                bL[np*2+0][0] = t[0]; bL[np*2+0][1] = t[2];
                bL[np*2+1][0] = t[1]; bL[np*2+1][1] = t[3];
            }
#pragma unroll
            for (int mt = 0; mt < 2; mt++)
#pragma unroll
                for (int nt = 0; nt < 4; nt++)
                    mma16816(acc[mt][nt], aH[mt], bH[nt]);
#pragma unroll
            for (int mt = 0; mt < 2; mt++)
#pragma unroll
                for (int nt = 0; nt < 4; nt++)
                    mma16816(acc[mt][nt], aL[mt], bH[nt]);
#pragma unroll
            for (int mt = 0; mt < 2; mt++)
#pragma unroll
                for (int nt = 0; nt < 4; nt++)
                    mma16816(acc[mt][nt], aH[mt], bL[nt]);
        }
        __syncthreads();
        if (c + 2 < NC) issue(c + 2);
    }

    const int er = m0 + wr*32 + (lane >> 2);
    const int ec = n0 + wc*32 + (lane & 3) * 2;
#pragma unroll
    for (int mt = 0; mt < 2; mt++)
#pragma unroll
        for (int nt = 0; nt < 4; nt++) {
            size_t i0 = (size_t)(er + mt*16) * N + ec + nt*8;
            size_t i1 = (size_t)(er + mt*16 + 8) * N + ec + nt*8;
            float2 r0 = make_float2(acc[mt][nt][0], acc[mt][nt][1]);
            float2 r1 = make_float2(acc[mt][nt][2], acc[mt][nt][3]);
            if (Add) {
                float2 a0 = *(const float2*)(Add + i0);
                float2 a1 = *(const float2*)(Add + i1);
                r0.x += a0.x; r0.y += a0.y;
                r1.x += a1.x; r1.y += a1.y;
            }
            *(float2*)(C + i0) = r0;
            *(float2*)(C + i1) = r1;
        }
}

// ---------------- merged RMSNorm + RoPE (q and k in one launch) ----------------
__global__ void rmsnorm_rope_qk(const float* __restrict__ src,
                                __nv_bfloat16* __restrict__ qh, __nv_bfloat16* __restrict__ ql,
                                __nv_bfloat16* __restrict__ kh, __nv_bfloat16* __restrict__ kl,
                                const float* __restrict__ gain)
{
    int warp = threadIdx.x >> 5, lane = threadIdx.x & 31;
    int item = blockIdx.x*4 + warp;
    const int NQ = B_*T_*H_;                      // 32768 q items first
    int colofs, nheads;
    __nv_bfloat16 *dsth, *dstl;
    bool isq = item < NQ;
    if (isq) { colofs = 0;  nheads = H_;   dsth = qh; dstl = ql; }
    else     { item -= NQ; colofs = D_; nheads = HKV_; dsth = kh; dstl = kl; }
    int h = item % nheads;
    int row = item / nheads;
    int tpos = row & (T_-1);
    int b = row >> 10;
    const float* p = src + (size_t)row * NQKV_ + colofs + h*64;
    float x1 = p[lane], x2 = p[lane+32];
    float ss = x1*x1 + x2*x2;
#pragma unroll
    for (int o = 16; o > 0; o >>= 1) ss += __shfl_xor_sync(0xffffffffu, ss, o);
    float r = rsqrtf(ss*(1.0f/64.0f) + 1e-6f);
    x1 *= r; x2 *= r;
    float invf = expf(-(float)lane * (9.210340371976184f/32.0f));
    float ang = (float)tpos * invf;
    float sv, cv;
    sincosf(ang, &sv, &cv);
    float g = isq ? gain[h] : 1.0f;
    float o1 = (x1*cv + x2*sv) * g;
    float o2 = (x2*cv - x1*sv) * g;
    size_t base = (((size_t)(b*nheads + h)*T_) + tpos)*64;
    __nv_bfloat16 h1 = __float2bfloat16(o1), h2 = __float2bfloat16(o2);
    dsth[base + lane]      = h1;
    dsth[base + lane + 32] = h2;
    dstl[base + lane]      = __float2bfloat16(o1 - __bfloat162float(h1));
    dstl[base + lane + 32] = __float2bfloat16(o2 - __bfloat162float(h2));
}

// ---------------- V transpose -> bf16 hi/lo (b,h,t,d) ----------------
__global__ void transpose_v_bf16()
{
    int idx = blockIdx.x*256 + threadIdx.x;
    int d = idx & 63;
    int h = (idx >> 6) & 3;
    int t = (idx >> 8) & 1023;
    int b = idx >> 18;
    int row = b*T_ + t;
    float v = g_qkv[(size_t)row * NQKV_ + (D_ + 256) + h*64 + d];
    size_t o = (((size_t)(b*HKV_ + h))*T_ + t)*64 + d;
    __nv_bfloat16 hv = __float2bfloat16(v);
    g_vbh[o] = hv;
    g_vbl[o] = __float2bfloat16(v - __bfloat162float(hv));
}

// ---------------- merged L2 norm (gq and gk in one launch) ----------------
__global__ void l2norm64_qk(const float* __restrict__ s1, float* __restrict__ d1,
                            const float* __restrict__ s2, float* __restrict__ d2)
{
    int warp = threadIdx.x >> 5, lane = threadIdx.x & 31;
    int item = blockIdx.x*4 + warp;
    const int N1 = B_*T_*HG_;                     // 16384
    const float* src; float* dst;
    if (item < N1) { src = s1; dst = d1; }
    else           { src = s2; dst = d2; item -= N1; }
    const float* p = src + (size_t)item*64;
    float x1 = p[lane], x2 = p[lane+32];
    float ss = x1*x1 + x2*x2;
#pragma unroll
    for (int o = 16; o > 0; o >>= 1) ss += __shfl_xor_sync(0xffffffffu, ss, o);
    float n = sqrtf(ss);
    float r = 1.0f / fmaxf(n, 1e-6f);
    dst[(size_t)item*64 + lane]      = x1*r;
    dst[(size_t)item*64 + lane + 32] = x2*r;
}

// ---------------- flash attention on mma.sync (unchanged) ----------------
static constexpr int ASTRIDE = 72;
static constexpr int AQPL = 64 * ASTRIDE * 2;
static constexpr int AKV0 = 2 * AQPL;
static constexpr int AKVPL = 32 * ASTRIDE * 2;
static constexpr int AKVSTG = 4 * AKVPL;
static constexpr int ATT_SMEM = AKV0 + 3 * AKVSTG;

__global__ void __launch_bounds__(128, 1) attn_mma()
{
    extern __shared__ __align__(128) char sm[];
    const uint32_t sb = smem_u32(sm);
    const int bx = blockIdx.x;
    const int qt = 15 - (bx >> 5);
    const int bh = bx & 31;
    const int b = bh >> 4, h = bh & 15;
    const int tid = threadIdx.x, w = tid >> 5, lane = tid & 31;
    const int gid = lane >> 2, tig = lane & 3;
    const int nkt = 2 * (qt + 1);
    const int row_base = qt*64 + w*16;

    const __nv_bfloat16* qsh = g_qbh + (((size_t)(b*H_ + h)*T_) + qt*64)*64;
    const __nv_bfloat16* qsl = g_qbl + (((size_t)(b*H_ + h)*T_) + qt*64)*64;
    const __nv_bfloat16* ksh = g_kbh + ((size_t)(b*HKV_ + (h>>2))*T_)*64;
    const __nv_bfloat16* ksl = g_kbl + ((size_t)(b*HKV_ + (h>>2))*T_)*64;
    const __nv_bfloat16* vsh = g_vbh + ((size_t)(b*HKV_ + (h>>2))*T_)*64;
    const __nv_bfloat16* vsl = g_vbl + ((size_t)(b*HKV_ + (h>>2))*T_)*64;

#pragma unroll
    for (int i = 0; i < 8; i++) {
        int idx = tid + i*128;
        int plane = idx >> 9, rem = idx & 511;
        int r = rem >> 3, c = rem & 7;
        const __nv_bfloat16* src = plane ? qsl : qsh;
        cp16(sb + plane*AQPL + r*144 + c*16, src + r*64 + c*8);
    }
    CP_COMMIT();

    auto loadkv = [&](int kt) {
        uint32_t base = sb + AKV0 + (kt % 3) * AKVSTG;
        const __nv_bfloat16* srcs[4] = { ksh, ksl, vsh, vsl };
#pragma unroll
        for (int p = 0; p < 4; p++) {
#pragma unroll
            for (int i = 0; i < 2; i++) {
                int idx = tid + i*128;
                int r = idx >> 3, c = idx & 7;
                cp16(base + p*AKVPL + r*144 + c*16, srcs[p] + (size_t)(kt*32 + r)*64 + c*8);
            }
        }
        CP_COMMIT();
    };

    loadkv(0);
    loadkv(1);

    CP_WAIT(2);
    __syncthreads();
    uint32_t QH[4][4], QL[4][4];
    {
        const uint32_t qro = (uint32_t)((w*16 + (lane & 15)) * 144 + ((lane >> 4) & 1) * 16);
#pragma unroll
        for (int kc = 0; kc < 4; kc++) {
            ldsm4(QH[kc], sb + 0*AQPL + qro + kc*32);
            ldsm4(QL[kc], sb + 1*AQPL + qro + kc*32);
        }
    }

    float o[8][4];
#pragma unroll
    for (int dn = 0; dn < 8; dn++)
#pragma unroll
        for (int j = 0; j < 4; j++) o[dn][j] = 0.f;
    float m0 = -1e30f, m1 = -1e30f, l0 = 0.f, l1 = 0.f;

    const uint32_t kro_base = (uint32_t)(((lane & 7) + ((lane >> 4) & 1) * 8) * 144
                                         + ((lane >> 3) & 1) * 16);
    const uint32_t vro_base = (uint32_t)(((lane & 7) + ((lane >> 3) & 1) * 8) * 144
                                         + ((lane >> 4) & 1) * 16);

    for (int kt = 0; kt < nkt; kt++) {
        if (kt + 1 < nkt) { CP_WAIT(1); } else { CP_WAIT(0); }
        __syncthreads();
        if (kt + 2 < nkt) loadkv(kt + 2);

        const int kt0 = kt * 32;
        if (kt0 > row_base + 15) continue;

        const uint32_t kvb = sb + AKV0 + (kt % 3) * AKVSTG;

        float acc[4][4];
#pragma unroll
        for (int nt = 0; nt < 4; nt++)
#pragma unroll
            for (int j = 0; j < 4; j++) acc[nt][j] = 0.f;

#pragma unroll
        for (int kc = 0; kc < 4; kc++) {
            uint32_t a0 = kvb + kro_base + kc*32;
            uint32_t a1 = a0 + 16*144;
            uint32_t h0[4], l0f[4], h1[4], l1f[4];
            ldsm4(h0, a0);
            ldsm4(l0f, a0 + AKVPL);
            ldsm4(h1, a1);
            ldsm4(l1f, a1 + AKVPL);
            mma16816(acc[0], QH[kc], &h0[0]);
            mma16816(acc[1], QH[kc], &h0[2]);
            mma16816(acc[2], QH[kc], &h1[0]);
            mma16816(acc[3], QH[kc], &h1[2]);
            mma16816(acc[0], QL[kc], &h0[0]);
            mma16816(acc[1], QL[kc], &h0[2]);
            mma16816(acc[2], QL[kc], &h1[0]);
            mma16816(acc[3], QL[kc], &h1[2]);
            mma16816(acc[0], QH[kc], &l0f[0]);
            mma16816(acc[1], QH[kc], &l0f[2]);
            mma16816(acc[2], QH[kc], &l1f[0]);
            mma16816(acc[3], QH[kc], &l1f[2]);
        }

        const int row0 = row_base + gid, row1 = row0 + 8;
        const bool domask = (kt0 + 31 > row_base);
#pragma unroll
        for (int nt = 0; nt < 4; nt++) {
            int kcol = kt0 + nt*8 + tig*2;
#pragma unroll
            for (int j = 0; j < 4; j++) acc[nt][j] *= 0.125f;
            if (domask) {
                if (kcol     > row0) acc[nt][0] = -1e30f;
                if (kcol + 1 > row0) acc[nt][1] = -1e30f;
                if (kcol     > row1) acc[nt][2] = -1e30f;
                if (kcol + 1 > row1) acc[nt][3] = -1e30f;
            }
        }

        float mx0 = -1e30f, mx1 = -1e30f;
#pragma unroll
        for (int nt = 0; nt < 4; nt++) {
            mx0 = fmaxf(mx0, fmaxf(acc[nt][0], acc[nt][1]));
            mx1 = fmaxf(mx1, fmaxf(acc[nt][2], acc[nt][3]));
        }
        mx0 = fmaxf(mx0, __shfl_xor_sync(0xffffffffu, mx0, 1));
        mx0 = fmaxf(mx0, __shfl_xor_sync(0xffffffffu, mx0, 2));
        mx1 = fmaxf(mx1, __shfl_xor_sync(0xffffffffu, mx1, 1));
        mx1 = fmaxf(mx1, __shfl_xor_sync(0xffffffffu, mx1, 2));
        float m0n = fmaxf(m0, mx0), m1n = fmaxf(m1, mx1);
        float c0r = __expf(m0 - m0n), c1r = __expf(m1 - m1n);
        m0 = m0n; m1 = m1n;
        l0 *= c0r; l1 *= c1r;
#pragma unroll
        for (int dn = 0; dn < 8; dn++) {
            o[dn][0] *= c0r; o[dn][1] *= c0r;
            o[dn][2] *= c1r; o[dn][3] *= c1r;
        }
        float s0 = 0.f, s1 = 0.f;
#pragma unroll
        for (int nt = 0; nt < 4; nt++) {
            acc[nt][0] = __expf(acc[nt][0] - m0);
            acc[nt][1] = __expf(acc[nt][1] - m0);
            acc[nt][2] = __expf(acc[nt][2] - m1);
            acc[nt][3] = __expf(acc[nt][3] - m1);
            s0 += acc[nt][0] + acc[nt][1];
            s1 += acc[nt][2] + acc[nt][3];
        }
        s0 += __shfl_xor_sync(0xffffffffu, s0, 1);
        s0 += __shfl_xor_sync(0xffffffffu, s0, 2);
        s1 += __shfl_xor_sync(0xffffffffu, s1, 1);
        s1 += __shfl_xor_sync(0xffffffffu, s1, 2);
        l0 += s0; l1 += s1;

        uint32_t PH[2][4], PL[2][4];
#pragma unroll
        for (int kk = 0; kk < 2; kk++) {
            float p00 = acc[2*kk][0],   p01 = acc[2*kk][1];
            float p02 = acc[2*kk][2],   p03 = acc[2*kk][3];
            float p10 = acc[2*kk+1][0], p11 = acc[2*kk+1][1];
            float p12 = acc[2*kk+1][2], p13 = acc[2*kk+1][3];
            PH[kk][0] = packb(p00, p01);
            PH[kk][1] = packb(p02, p03);
            PH[kk][2] = packb(p10, p11);
            PH[kk][3] = packb(p12, p13);
            PL[kk][0] = packb(p00 - __bfloat162float(__float2bfloat16(p00)),
                              p01 - __bfloat162float(__float2bfloat16(p01)));
            PL[kk][1] = packb(p02 - __bfloat162float(__float2bfloat16(p02)),
                              p03 - __bfloat162float(__float2bfloat16(p03)));
            PL[kk][2] = packb(p10 - __bfloat162float(__float2bfloat16(p10)),
                              p11 - __bfloat162float(__float2bfloat16(p11)));
            PL[kk][3] = packb(p12 - __bfloat162float(__float2bfloat16(p12)),
                              p13 - __bfloat162float(__float2bfloat16(p13)));
        }

#pragma unroll
        for (int kk = 0; kk < 2; kk++) {
#pragma unroll
            for (int dcp = 0; dcp < 2; dcp++) {
                uint32_t aA = kvb + 2*AKVPL + vro_base + kk*16*144 + (dcp*2)*32;
                uint32_t aB = aA + 32;
                uint32_t vhA[4], vlA[4], vhB[4], vlB[4];
                ldsm4t(vhA, aA);
                ldsm4t(vlA, aA + AKVPL);
                ldsm4t(vhB, aB);
                ldsm4t(vlB, aB + AKVPL);
                float (&oA0)[4] = o[dcp*4+0];
                float (&oA1)[4] = o[dcp*4+1];
                float (&oB0)[4] = o[dcp*4+2];
                float (&oB1)[4] = o[dcp*4+3];
                mma16816(oA0, PH[kk], &vhA[0]);
                mma16816(oA1, PH[kk], &vhA[2]);
                mma16816(oB0, PH[kk], &vhB[0]);
                mma16816(oB1, PH[kk], &vhB[2]);
                mma16816(oA0, PL[kk], &vhA[0]);
                mma16816(oA1, PL[kk], &vhA[2]);
                mma16816(oB0, PL[kk], &vhB[0]);
                mma16816(oB1, PL[kk], &vhB[2]);
                mma16816(oA0, PH[kk], &vlA[0]);
                mma16816(oA1, PH[kk], &vlA[2]);
                mma16816(oB0, PH[kk], &vlB[0]);
                mma16816(oB1, PH[kk], &vlB[2]);
            }
        }
    }

    const float i0 = 1.f / l0, i1 = 1.f / l1;
    const int grow0 = b*T_ + row_base + gid;
#pragma unroll
    for (int dn = 0; dn < 8; dn++) {
        int dcp = dn >> 2, sub = dn & 3;
        int col = h*64 + dcp*32 + sub*8 + tig*2;
        float a0 = o[dn][0]*i0, a1 = o[dn][1]*i0;
        float a2 = o[dn][2]*i1, a3 = o[dn][3]*i1;
        __nv_bfloat16 h0 = __float2bfloat16(a0), h1 = __float2bfloat16(a1);
        __nv_bfloat16 h2 = __float2bfloat16(a2), h3 = __float2bfloat16(a3);
        size_t p0 = (size_t)grow0 * D_ + col;
        size_t p1 = (size_t)(grow0 + 8) * D_ + col;
        *(__nv_bfloat162*)(g_yh + p0) = __nv_bfloat162(h0, h1);
        *(__nv_bfloat162*)(g_yh + p1) = __nv_bfloat162(h2, h3);
        *(__nv_bfloat162*)(g_yl + p0) = __nv_bfloat162(
            __float2bfloat16(a0 - __bfloat162float(h0)),
            __float2bfloat16(a1 - __bfloat162float(h1)));
        *(__nv_bfloat162*)(g_yl + p1) = __nv_bfloat162(
            __float2bfloat16(a2 - __bfloat162float(h2)),
            __float2bfloat16(a3 - __bfloat162float(h3)));
    }
}

// ---------------- GDN v6 (proven best, 64-step chunks / 74.7KB): deferred-output pipeline ----------------
static constexpr int GDN_CH = 64;
static constexpr int GDN_KS = 0;
static constexpr int GDN_QS = 16384;
static constexpr int GDN_VS = 32768;
static constexpr int GDN_AS = 36864;
static constexpr int GDN_BS = 37120;
static constexpr int GDN_BUF = 37376;
static constexpr int GDN_SMEM = 2 * GDN_BUF;

__global__ void __launch_bounds__(128) gdn_kernel(const float* __restrict__ gv,
    const float* __restrict__ alpha, const float* __restrict__ beta,
    float* __restrict__ gout)
{
    extern __shared__ __align__(16) char sm[];
    const int bh = blockIdx.x >> 3;
    const int cc = blockIdx.x & 7;
    const int b = bh >> 3, h = bh & 7;
    const int tid = threadIdx.x;
    const int coll = tid >> 3;
    const int col = cc*16 + coll;
    const int e = tid & 7;

    const float* kbase = g_kn + ((size_t)(b*T_)*HG_ + h)*64;
    const float* qbase = g_qn + ((size_t)(b*T_)*HG_ + h)*64;
    const float* vbase = gv    + ((size_t)(b*T_)*HG_ + h)*128 + cc*16;
    const float* abase = alpha + (size_t)b*T_*HG_ + h;
    const float* bbase = beta  + (size_t)b*T_*HG_ + h;
    float* op = gout + (size_t)b*T_*D_ + h*DV_ + col;

    const uint32_t sb = smem_u32(sm);

    auto issue = [&](int ch) {
        uint32_t dst = sb + (uint32_t)(ch & 1) * GDN_BUF;
        const int t0 = ch * GDN_CH;
#pragma unroll
        for (int i = 0; i < 8; i++) {
            int idx = tid + i*128;
            int r = idx >> 4, c = idx & 15;
            cp16(dst + GDN_KS + (uint32_t)(r*256 + c*16), kbase + (size_t)(t0+r)*512 + c*4);
            cp16(dst + GDN_QS + (uint32_t)(r*256 + c*16), qbase + (size_t)(t0+r)*512 + c*4);
        }
#pragma unroll
        for (int i = 0; i < 2; i++) {
            int idx = tid + i*128;
            int r = idx >> 2, c = idx & 3;
            cp16(dst + GDN_VS + (uint32_t)(r*64 + c*16), vbase + (size_t)(t0+r)*1024 + c*4);
        }
        if (tid < 64) {
            cp4(dst + GDN_AS + (uint32_t)tid*4, abase + (size_t)(t0+tid)*8);
            cp4(dst + GDN_BS + (uint32_t)tid*4, bbase + (size_t)(t0+tid)*8);
        }
        CP_COMMIT();
    };

    float S[8];
#pragma unroll
    for (int i = 0; i < 8; i++) S[i] = 0.f;
    float pdot = 0.f;

    issue(0);
    issue(1);
    const int NCH = T_ / GDN_CH;

    for (int ch = 0; ch < NCH; ch++) {
        if (ch + 1 < NCH) { CP_WAIT(1); } else { CP_WAIT(0); }
        __syncthreads();
        const char* bufp = sm + (ch & 1) * GDN_BUF;
        const float* sk = (const float*)(bufp + GDN_KS);
        const float* sq = (const float*)(bufp + GDN_QS);
        const float* sv = (const float*)(bufp + GDN_VS);
        const float* sa = (const float*)(bufp + GDN_AS);
        const float* sbt = (const float*)(bufp + GDN_BS);

        float4 ck0 = *(const float4*)(sk + e*8);
        float4 ck1 = *(const float4*)(sk + e*8 + 4);
        float4 cq0 = *(const float4*)(sq + e*8);
        float4 cq1 = *(const float4*)(sq + e*8 + 4);
        float cv = sv[coll];
        float ca = sa[0], cb = sbt[0];

#pragma unroll 4
        for (int t = 0; t < GDN_CH; t++) {
            float4 nk0 = ck0, nk1 = ck1, nq0 = cq0, nq1 = cq1;
            float nv = cv, na = ca, nb = cb;
            if (t + 1 < GDN_CH) {
                nk0 = *(const float4*)(sk + (t+1)*64 + e*8);
                nk1 = *(const float4*)(sk + (t+1)*64 + e*8 + 4);
                nq0 = *(const float4*)(sq + (t+1)*64 + e*8);
                nq1 = *(const float4*)(sq + (t+1)*64 + e*8 + 4);
                nv = sv[(t+1)*16 + coll];
                na = sa[t+1]; nb = sbt[t+1];
            }

            float d0 = ck0.x*S[0] + ck0.y*S[1];
            float d1 = ck0.z*S[2] + ck0.w*S[3];
            float d2 = ck1.x*S[4] + ck1.y*S[5];
            float d3 = ck1.z*S[6] + ck1.w*S[7];
            float kS = (d0+d1) + (d2+d3);

            float p0 = ca*S[0], p1 = ca*S[1], p2 = ca*S[2], p3 = ca*S[3];
            float p4 = ca*S[4], p5 = ca*S[5], p6 = ca*S[6], p7 = ca*S[7];

            float s1 = __shfl_xor_sync(0xffffffffu, kS, 1);
            float r1 = __shfl_xor_sync(0xffffffffu, pdot, 1);
            kS += s1; pdot += r1;
            float s2 = __shfl_xor_sync(0xffffffffu, kS, 2);
            float r2 = __shfl_xor_sync(0xffffffffu, pdot, 2);
            kS += s2; pdot += r2;
            float s4 = __shfl_xor_sync(0xffffffffu, kS, 4);
            float r4 = __shfl_xor_sync(0xffffffffu, pdot, 4);
            kS += s4; pdot += r4;

            const int gt = ch*GDN_CH + t;
            if (e == 0 && gt > 0) op[(size_t)(gt-1) * D_] = pdot;

            float coef = fmaf(-ca*cb, kS, cv);
            S[0] = fmaf(coef, ck0.x, p0);
            S[1] = fmaf(coef, ck0.y, p1);
            S[2] = fmaf(coef, ck0.z, p2);
            S[3] = fmaf(coef, ck0.w, p3);
            S[4] = fmaf(coef, ck1.x, p4);
            S[5] = fmaf(coef, ck1.y, p5);
            S[6] = fmaf(coef, ck1.z, p6);
            S[7] = fmaf(coef, ck1.w, p7);

            float e0 = S[0]*cq0.x + S[1]*cq0.y;
            float e1 = S[2]*cq0.z + S[3]*cq0.w;
            float e2 = S[4]*cq1.x + S[5]*cq1.y;
            float e3 = S[6]*cq1.z + S[7]*cq1.w;
            pdot = (e0+e1) + (e2+e3);

            ck0 = nk0; ck1 = nk1; cq0 = nq0; cq1 = nq1;
            cv = nv; ca = na; cb = nb;
        }
        __syncthreads();
        if (ch + 2 < NCH) issue(ch + 2);
    }

    pdot += __shfl_xor_sync(0xffffffffu, pdot, 1);
    pdot += __shfl_xor_sync(0xffffffffu, pdot, 2);
    pdot += __shfl_xor_sync(0xffffffffu, pdot, 4);
    if (e == 0) op[(size_t)(T_-1) * D_] = pdot;
}

// ---------------- launch: R15 fork structure, merged small kernels ----------------
extern "C" void kernel_launch(void* const* d_in, const int* in_sizes, int n_in,
                              void* d_out, int out_size)
{
    const float* x     = (const float*)d_in[0];
    const float* Wq    = (const float*)d_in[1];
    const float* Wk    = (const float*)d_in[2];
    const float* Wv    = (const float*)d_in[3];
    const float* Wo    = (const float*)d_in[4];
    const float* qg    = (const float*)d_in[5];
    const float* gq    = (const float*)d_in[6];
    const float* gk    = (const float*)d_in[7];
    const float* gv    = (const float*)d_in[8];
    const float* alpha = (const float*)d_in[9];
    const float* beta  = (const float*)d_in[10];
    float* out = (float*)d_out;

    float *qkv,*qn,*kn,*gdn;
    cudaGetSymbolAddress((void**)&qkv, g_qkv);
    cudaGetSymbolAddress((void**)&qn, g_qn);
    cudaGetSymbolAddress((void**)&kn, g_kn);
    cudaGetSymbolAddress((void**)&gdn, g_gdn);

    __nv_bfloat16 *xh,*xl,*wh,*wl,*woh,*wol,*yh,*yl,*qbh,*qbl,*kbh,*kbl;
    cudaGetSymbolAddress((void**)&xh, g_xh);   cudaGetSymbolAddress((void**)&xl, g_xl);
    cudaGetSymbolAddress((void**)&wh, g_wh);   cudaGetSymbolAddress((void**)&wl, g_wl);
    cudaGetSymbolAddress((void**)&woh, g_woh); cudaGetSymbolAddress((void**)&wol, g_wol);
    cudaGetSymbolAddress((void**)&yh, g_yh);   cudaGetSymbolAddress((void**)&yl, g_yl);
    cudaGetSymbolAddress((void**)&qbh, g_qbh); cudaGetSymbolAddress((void**)&qbl, g_qbl);
    cudaGetSymbolAddress((void**)&kbh, g_kbh); cudaGetSymbolAddress((void**)&kbl, g_kbl);

    cudaFuncSetAttribute(gemm_mma, cudaFuncAttributeMaxDynamicSharedMemorySize, GEMM_SMEM);
    cudaFuncSetAttribute(attn_mma, cudaFuncAttributeMaxDynamicSharedMemorySize, ATT_SMEM);
    cudaFuncSetAttribute(gdn_kernel, cudaFuncAttributeMaxDynamicSharedMemorySize, GDN_SMEM);

    cudaStream_t s2;
    cudaEvent_t evFork, evJoin;
    cudaStreamCreateWithFlags(&s2, cudaStreamNonBlocking);
    cudaEventCreateWithFlags(&evFork, cudaEventDisableTiming);
    cudaEventCreateWithFlags(&evJoin, cudaEventDisableTiming);

    cudaEventRecord(evFork, 0);
    cudaStreamWaitEvent(s2, evFork, 0);

    // ---- GDN branch on s2 (merged l2norm) ----
    l2norm64_qk<<<(2*B_*T_*HG_)/4, 128, 0, s2>>>(gq, qn, gk, kn);
    gdn_kernel<<<128, 128, GDN_SMEM, s2>>>(gv, alpha, beta, gdn);
    cudaEventRecord(evJoin, s2);

    // ---- attention branch on default stream ----
    split_w_qkv<<<NQKV_*D_/4/256, 256>>>(Wq, Wk, Wv, wh, wl);
    split_bf16<<<MT_*D_/4/256, 256>>>(x, xh, xl, MT_*D_/4);
    split_bf16<<<D_*D_/4/256, 256>>>(Wo, woh, wol, D_*D_/4);

    gemm_mma<<<dim3(NQKV_/64, MT_/128), 256, GEMM_SMEM>>>(
        xh, xl, wh, wl, qkv, (const float*)nullptr, MT_, NQKV_, D_);

    rmsnorm_rope_qk<<<(B_*T_*(H_+HKV_))/4, 128>>>(qkv, qbh, qbl, kbh, kbl, qg);
    transpose_v_bf16<<<(B_*T_*HKV_*HD_)/256, 256>>>();

    attn_mma<<<512, 128, ATT_SMEM>>>();

    // ---- join: Wo projection + GDN add needs both branches ----
    cudaStreamWaitEvent(0, evJoin, 0);
    gemm_mma<<<dim3(D_/64, MT_/128), 256, GEMM_SMEM>>>(
        yh, yl, woh, wol, out, gdn, MT_, D_, D_);
}